// round 7
// baseline (speedup 1.0000x reference)
#include <cuda_runtime.h>
#include <cuda_fp16.h>
#include <cmath>

// Problem constants
#define BATCH   2
#define SEQ     2048
#define DIM     1024
#define NH      16
#define DKH     16
#define DVH     64
#define NTOK    (BATCH*SEQ)          // 4096
#define QCOLS   (NH*DKH)             // 256
#define KVCOLS  (NH*(DKH+DVH))       // 1280
#define OCOLS   (NH*DVH)             // 1024
#define PCOLS   1536                 // 256 q + 256 k + 1024 v (permuted)

// ---------------- scratch ----------------
__device__ __half g_tokh[NTOK * DIM];
__device__ __half g_wc  [PCOLS * DIM];
__device__ __half g_wot [DIM * OCOLS];
__device__ __half g_qn[BATCH*NH*SEQ*DKH];
__device__ __half g_kn[BATCH*NH*SEQ*DKH];
__device__ __half g_vh[BATCH*NH*SEQ*DVH];
__device__ __half g_aoh[NTOK * OCOLS];

// ---------------- helpers ----------------
__device__ __forceinline__ unsigned packh2(float a, float b){
    __half2 h = __floats2half2_rn(a, b);
    return *(unsigned*)&h;
}
__device__ __forceinline__ unsigned sptr(const void* p){
    return (unsigned)__cvta_generic_to_shared(p);
}
__device__ __forceinline__ void ldm4(unsigned r[4], unsigned a){
    asm volatile("ldmatrix.sync.aligned.m8n8.x4.shared.b16 {%0,%1,%2,%3}, [%4];"
        : "=r"(r[0]),"=r"(r[1]),"=r"(r[2]),"=r"(r[3]) : "r"(a));
}
__device__ __forceinline__ void ldm4t(unsigned r[4], unsigned a){
    asm volatile("ldmatrix.sync.aligned.m8n8.x4.trans.shared.b16 {%0,%1,%2,%3}, [%4];"
        : "=r"(r[0]),"=r"(r[1]),"=r"(r[2]),"=r"(r[3]) : "r"(a));
}
__device__ __forceinline__ void mma16(float* c, const unsigned* a, const unsigned* b){
    asm volatile("mma.sync.aligned.m16n8k16.row.col.f32.f16.f16.f32 "
        "{%0,%1,%2,%3},{%4,%5,%6,%7},{%8,%9},{%0,%1,%2,%3};\n"
        : "+f"(c[0]),"+f"(c[1]),"+f"(c[2]),"+f"(c[3])
        : "r"(a[0]),"r"(a[1]),"r"(a[2]),"r"(a[3]),"r"(b[0]),"r"(b[1]));
}
__device__ __forceinline__ void cpa16(unsigned dst, const void* src){
    asm volatile("cp.async.cg.shared.global [%0], [%1], 16;" :: "r"(dst), "l"(src));
}
#define CP_COMMIT() asm volatile("cp.async.commit_group;" ::: "memory")
#define CP_WAIT0()  asm volatile("cp.async.wait_group 0;" ::: "memory")
#define CP_WAIT1()  asm volatile("cp.async.wait_group 1;" ::: "memory")

// ---------------- prep kernels ----------------
__global__ __launch_bounds__(256) void cvt_f2h(const float* __restrict__ src,
                                              __half* __restrict__ dst, int n8)
{
    int i = blockIdx.x * blockDim.x + threadIdx.x;
    if (i >= n8) return;
    float4 a = ((const float4*)src)[2*i];
    float4 b = ((const float4*)src)[2*i+1];
    uint4 p = make_uint4(packh2(a.x,a.y), packh2(a.z,a.w),
                         packh2(b.x,b.y), packh2(b.z,b.w));
    ((uint4*)dst)[i] = p;
}

__global__ __launch_bounds__(256) void wprep(const float* __restrict__ Wq,
                                             const float* __restrict__ Wkv,
                                             __half* __restrict__ Wc)
{
    __shared__ float ts[32][33];
    const int n0 = blockIdx.x * 32, k0 = blockIdx.y * 32;
    const int tx = threadIdx.x & 31, ty = threadIdx.x >> 5;
    {
        const int n = n0 + tx;
        const float* W; int c, ld;
        if (n < 256)      { W = Wq;  ld = QCOLS;  c = n; }
        else if (n < 512) { int j = n - 256; W = Wkv; ld = KVCOLS; c = (j >> 4) * 80 + (j & 15); }
        else              { int j = n - 512; W = Wkv; ld = KVCOLS; c = (j >> 6) * 80 + 16 + (j & 63); }
        #pragma unroll
        for (int i = 0; i < 32; i += 8)
            ts[ty + i][tx] = W[(size_t)(k0 + ty + i) * ld + c];
    }
    __syncthreads();
    #pragma unroll
    for (int i = 0; i < 32; i += 8)
        Wc[(size_t)(n0 + ty + i) * DIM + k0 + tx] = __float2half(ts[tx][ty + i]);
}

__global__ __launch_bounds__(256) void wtrans(const float* __restrict__ W,
                                              __half* __restrict__ Wt, int N, int K)
{
    __shared__ float ts[32][33];
    const int n0 = blockIdx.x * 32, k0 = blockIdx.y * 32;
    const int tx = threadIdx.x & 31, ty = threadIdx.x >> 5;
    #pragma unroll
    for (int i = 0; i < 32; i += 8)
        ts[ty + i][tx] = W[(size_t)(k0 + ty + i) * N + n0 + tx];
    __syncthreads();
    #pragma unroll
    for (int i = 0; i < 32; i += 8)
        Wt[(size_t)(n0 + ty + i) * K + k0 + tx] = __float2half(ts[tx][ty + i]);
}

// ============ shared GEMM core: 128x128 block, 8 warps, warp 32x64 =========
// 3-stage cp.async pipeline, BK=32. A[M][K], Bt[N][K] both fp16 row-major.
// Tiles live in DYNAMIC shared memory (60 KB > 48 KB static limit).
#define GAS 20
#define GROW (128 * GAS)            // u32 per stage per array
#define GSTG (GROW * 4)             // bytes per stage per array
#define SMEM_GEMM (2 * 3 * GSTG)    // 61440 bytes

// As(st,r,c) index helpers into dynsmem
#define ASI(st, r, c) dynsmem[(st) * GROW + (r) * GAS + (c)]
#define BSI(st, r, c) dynsmem[3 * GROW + (st) * GROW + (r) * GAS + (c)]

#define CORE_LOAD(AP, BP, K_, k0_, st_) do {                                     \
    cpa16(sptr(&ASI(st_, ar, ac4*4)),      &(AP)[(size_t)(m0+ar)*(K_) + (k0_) + ac4*8]);     \
    cpa16(sptr(&ASI(st_, ar+64, ac4*4)),   &(AP)[(size_t)(m0+ar+64)*(K_) + (k0_) + ac4*8]);  \
    cpa16(sptr(&BSI(st_, ar, ac4*4)),      &(BP)[(size_t)(n0+ar)*(K_) + (k0_) + ac4*8]);     \
    cpa16(sptr(&BSI(st_, ar+64, ac4*4)),   &(BP)[(size_t)(n0+ar+64)*(K_) + (k0_) + ac4*8]);  \
} while(0)

#define CORE_COMPUTE(oa_) do {                                                   \
    _Pragma("unroll")                                                            \
    for (int ks = 0; ks < 2; ks++) {                                             \
        const unsigned cb = (oa_) + ks * 32;                                     \
        unsigned a0[4], a1[4], b0[4], b1[4], b2[4], b3[4];                       \
        ldm4(a0, adrA0 + cb);  ldm4(a1, adrA1 + cb);                             \
        ldm4(b0, adrB0 + cb);  ldm4(b1, adrB0 + cb + 16);                        \
        ldm4(b2, adrB1 + cb);  ldm4(b3, adrB1 + cb + 16);                        \
        _Pragma("unroll")                                                        \
        for (int nt = 0; nt < 4; nt++) {                                         \
            unsigned bb[2] = { b0[nt], b1[nt] };                                 \
            mma16(Co[0][nt], a0, bb);                                            \
            mma16(Co[1][nt], a1, bb);                                            \
        }                                                                        \
        _Pragma("unroll")                                                        \
        for (int nt = 0; nt < 4; nt++) {                                         \
            unsigned bb[2] = { b2[nt], b3[nt] };                                 \
            mma16(Co[0][4+nt], a0, bb);                                          \
            mma16(Co[1][4+nt], a1, bb);                                          \
        }                                                                        \
    }                                                                            \
} while(0)

// ---------------- fused projection GEMM + l2norm + head scatter ------------
__global__ __launch_bounds__(256) void proj_gemm(
    const __half* __restrict__ A, const __half* __restrict__ Bt,
    __half* __restrict__ gq, __half* __restrict__ gk, __half* __restrict__ gv)
{
    extern __shared__ unsigned dynsmem[];

    const int t = threadIdx.x;
    const int w = t >> 5, lane = t & 31, g = lane >> 2, tig = lane & 3;
    const int wm = (w >> 1) * 32, wn = (w & 1) * 64;
    const int m0 = blockIdx.y * 128, n0 = blockIdx.x * 128;
    const int li = lane & 7, lj = lane >> 3;
    const int ar = t >> 2, ac4 = t & 3;

    const unsigned adrA0 = sptr(&ASI(0, wm + (lj & 1) * 8 + li, (lj >> 1) * 4));
    const unsigned adrA1 = adrA0 + 16 * GAS * 4;
    const unsigned adrB0 = sptr(&BSI(0, wn + lj * 8 + li, 0));
    const unsigned adrB1 = adrB0 + 32 * GAS * 4;

    CORE_LOAD(A, Bt, DIM, 0, 0);  CP_COMMIT();
    CORE_LOAD(A, Bt, DIM, 32, 1); CP_COMMIT();

    float Co[2][8][4] = {};
    const int KT = DIM / 32;
    for (int kt = 0; kt < KT; kt++) {
        if (kt + 1 < KT) CP_WAIT1(); else CP_WAIT0();
        __syncthreads();
        if (kt + 2 < KT) { CORE_LOAD(A, Bt, DIM, (kt + 2) * 32, (kt + 2) % 3); CP_COMMIT(); }
        CORE_COMPUTE((unsigned)((kt % 3) * GSTG));
    }

    // ---- epilogue: per-row group norms (registers + shfl only) ----
    const int region = (n0 < 256) ? 0 : (n0 < 512 ? 1 : 2);
    #pragma unroll
    for (int mt = 0; mt < 2; mt++)
        #pragma unroll
        for (int rh = 0; rh < 2; rh++) {
            const int r = wm + mt * 16 + g + rh * 8;
            const int mrow = m0 + r;
            const int b_ = mrow >> 11, seq = mrow & (SEQ - 1);

            float p[4];
            #pragma unroll
            for (int g2 = 0; g2 < 4; g2++) {
                float x0 = Co[mt][2*g2  ][2*rh], x1 = Co[mt][2*g2  ][2*rh+1];
                float y0 = Co[mt][2*g2+1][2*rh], y1 = Co[mt][2*g2+1][2*rh+1];
                float s = x0*x0 + x1*x1 + y0*y0 + y1*y1;
                s += __shfl_xor_sync(~0u, s, 1);
                s += __shfl_xor_sync(~0u, s, 2);
                p[g2] = s;
            }
            float scv = 0.f;
            if (region == 2)
                scv = 1.f / fmaxf(sqrtf(p[0]+p[1]+p[2]+p[3]), 1e-12f);

            #pragma unroll
            for (int nt = 0; nt < 8; nt++) {
                float sc = (region == 2) ? scv
                         : 1.f / fmaxf(sqrtf(p[nt >> 1]), 1e-12f);
                const int n = n0 + wn + nt * 8 + 2 * tig;
                unsigned pv = packh2(Co[mt][nt][2*rh] * sc, Co[mt][nt][2*rh+1] * sc);
                if (region == 0) {
                    int h = n >> 4, d = n & 15;
                    *(unsigned*)&gq[((size_t)(b_*NH + h) * SEQ + seq) * DKH + d] = pv;
                } else if (region == 1) {
                    int j = n - 256, h = j >> 4, d = j & 15;
                    *(unsigned*)&gk[((size_t)(b_*NH + h) * SEQ + seq) * DKH + d] = pv;
                } else {
                    int j = n - 512, h = j >> 6, d = j & 63;
                    *(unsigned*)&gv[((size_t)(b_*NH + h) * SEQ + seq) * DVH + d] = pv;
                }
            }
        }
}

// ---------------- final GEMM: C_f32 = A @ Bt^T ----------------
__global__ __launch_bounds__(256) void gemm_f16(
    const __half* __restrict__ A, const __half* __restrict__ Bt,
    float* __restrict__ C, int M, int N, int K)
{
    extern __shared__ unsigned dynsmem[];

    const int t = threadIdx.x;
    const int w = t >> 5, lane = t & 31, g = lane >> 2, tig = lane & 3;
    const int wm = (w >> 1) * 32, wn = (w & 1) * 64;
    const int m0 = blockIdx.y * 128, n0 = blockIdx.x * 128;
    const int li = lane & 7, lj = lane >> 3;
    const int ar = t >> 2, ac4 = t & 3;

    const unsigned adrA0 = sptr(&ASI(0, wm + (lj & 1) * 8 + li, (lj >> 1) * 4));
    const unsigned adrA1 = adrA0 + 16 * GAS * 4;
    const unsigned adrB0 = sptr(&BSI(0, wn + lj * 8 + li, 0));
    const unsigned adrB1 = adrB0 + 32 * GAS * 4;

    CORE_LOAD(A, Bt, K, 0, 0);  CP_COMMIT();
    CORE_LOAD(A, Bt, K, 32, 1); CP_COMMIT();

    float Co[2][8][4] = {};
    const int KT = K / 32;
    for (int kt = 0; kt < KT; kt++) {
        if (kt + 1 < KT) CP_WAIT1(); else CP_WAIT0();
        __syncthreads();
        if (kt + 2 < KT) { CORE_LOAD(A, Bt, K, (kt + 2) * 32, (kt + 2) % 3); CP_COMMIT(); }
        CORE_COMPUTE((unsigned)((kt % 3) * GSTG));
    }

    #pragma unroll
    for (int mt = 0; mt < 2; mt++)
        #pragma unroll
        for (int nt = 0; nt < 8; nt++) {
            int r = m0 + wm + mt * 16 + g;
            int c = n0 + wn + nt * 8 + 2 * tig;
            *(float2*)&C[(size_t)r * N + c]       = make_float2(Co[mt][nt][0], Co[mt][nt][1]);
            *(float2*)&C[(size_t)(r + 8) * N + c] = make_float2(Co[mt][nt][2], Co[mt][nt][3]);
        }
}

// ---------------- fused attention: register-resident S ----------------
#define AQS  12
#define AVSH 72
__global__ __launch_bounds__(256) void attn_f16(
    const __half* __restrict__ gq, const __half* __restrict__ gk,
    const __half* __restrict__ gv, __half* __restrict__ gao)
{
    __shared__ unsigned Qs[128][AQS];
    __shared__ unsigned Ks[2][64][AQS];
    __shared__ __half   Vs[2][64][AVSH];

    const int t = threadIdx.x;
    const int w = t >> 5, lane = t & 31, g = lane >> 2, tig = lane & 3;
    const int wm = w * 16;
    const int bh = blockIdx.y, q0 = blockIdx.x * 128;
    const int li = lane & 7, lj = lane >> 3;

    const __half* qb = gq + (size_t)bh * SEQ * DKH;
    const __half* kb = gk + (size_t)bh * SEQ * DKH;
    const __half* vb = gv + (size_t)bh * SEQ * DVH;

    {
        int r = t >> 1, hf = t & 1;
        *(uint4*)&Qs[r][hf * 4] = *(const uint4*)&qb[(size_t)(q0 + r) * DKH + hf * 8];
    }

    const int kr = t >> 1, khf = t & 1;
    const int vr = t >> 3, vc = (t & 7) * 8;
    #define ATTN_LOAD(k0_, buf_) do {                                            \
        if (t < 128)                                                             \
            cpa16(sptr(&Ks[buf_][kr][khf*4]), &kb[(size_t)((k0_)+kr)*DKH + khf*8]); \
        cpa16(sptr(&Vs[buf_][vr][vc]),      &vb[(size_t)((k0_)+vr)*DVH + vc]);   \
        cpa16(sptr(&Vs[buf_][vr+32][vc]),   &vb[(size_t)((k0_)+vr+32)*DVH + vc]);\
    } while(0)

    ATTN_LOAD(0, 0);
    CP_COMMIT();
    __syncthreads();

    unsigned aq[4];
    ldm4(aq, sptr(&Qs[wm + (lj & 1) * 8 + li][(lj >> 1) * 4]));

    const unsigned KBUF = 64 * AQS * 4, VBUF = 64 * AVSH * 2;
    const unsigned adrK = sptr(&Ks[0][lj * 8 + li][0]);
    const unsigned adrV = sptr(&Vs[0][(lj & 1) * 8 + li][(lj >> 1) * 8]);

    float Co[8][4] = {};

    const int NT = SEQ / 64;
    for (int kt = 0; kt < NT; kt++) {
        CP_WAIT0();
        __syncthreads();
        if (kt + 1 < NT) { ATTN_LOAD((kt + 1) * 64, (kt + 1) & 1); CP_COMMIT(); }
        const unsigned kbase = adrK + (kt & 1) * KBUF;
        const unsigned vbase = adrV + (kt & 1) * VBUF;

        float Cs[8][4] = {};
        {
            unsigned b0[4], b1[4], b2[4], b3[4];
            ldm4(b0, kbase);
            ldm4(b1, kbase + 16);
            ldm4(b2, kbase + 32 * AQS * 4);
            ldm4(b3, kbase + 32 * AQS * 4 + 16);
            #pragma unroll
            for (int nt = 0; nt < 4; nt++) {
                unsigned bA[2] = { b0[nt], b1[nt] };
                unsigned bB[2] = { b2[nt], b3[nt] };
                mma16(Cs[nt],     aq, bA);
                mma16(Cs[4 + nt], aq, bB);
            }
        }

        unsigned sf[4][4];
        #pragma unroll
        for (int ks = 0; ks < 4; ks++) {
            float r0 = Cs[2*ks][0];   r0 = r0 > 0.f ? r0*r0 : 0.f;
            float r1 = Cs[2*ks][1];   r1 = r1 > 0.f ? r1*r1 : 0.f;
            float r2 = Cs[2*ks][2];   r2 = r2 > 0.f ? r2*r2 : 0.f;
            float r3 = Cs[2*ks][3];   r3 = r3 > 0.f ? r3*r3 : 0.f;
            float r4 = Cs[2*ks+1][0]; r4 = r4 > 0.f ? r4*r4 : 0.f;
            float r5 = Cs[2*ks+1][1]; r5 = r5 > 0.f ? r5*r5 : 0.f;
            float r6 = Cs[2*ks+1][2]; r6 = r6 > 0.f ? r6*r6 : 0.f;
            float r7 = Cs[2*ks+1][3]; r7 = r7 > 0.f ? r7*r7 : 0.f;
            sf[ks][0] = packh2(r0, r1);
            sf[ks][1] = packh2(r2, r3);
            sf[ks][2] = packh2(r4, r5);
            sf[ks][3] = packh2(r6, r7);
        }

        #pragma unroll
        for (int ks = 0; ks < 4; ks++) {
            const unsigned vk = vbase + ks * 16 * AVSH * 2;
            #pragma unroll
            for (int j = 0; j < 4; j++) {
                unsigned vv[4];
                ldm4t(vv, vk + j * 32);
                unsigned bA[2] = { vv[0], vv[1] };
                unsigned bB[2] = { vv[2], vv[3] };
                mma16(Co[2*j],     sf[ks], bA);
                mma16(Co[2*j + 1], sf[ks], bB);
            }
        }
        __syncthreads();
    }

    float s0 = 0.f, s1 = 0.f;
    #pragma unroll
    for (int nt = 0; nt < 8; nt++) {
        s0 += Co[nt][0]*Co[nt][0] + Co[nt][1]*Co[nt][1];
        s1 += Co[nt][2]*Co[nt][2] + Co[nt][3]*Co[nt][3];
    }
    s0 += __shfl_xor_sync(~0u, s0, 1); s0 += __shfl_xor_sync(~0u, s0, 2);
    s1 += __shfl_xor_sync(~0u, s1, 1); s1 += __shfl_xor_sync(~0u, s1, 2);
    float n0s = sqrtf(s0), n1s = sqrtf(s1);
    float sc0 = tanhf(n0s) / fmaxf(n0s, 1e-12f);
    float sc1 = tanhf(n1s) / fmaxf(n1s, 1e-12f);

    const int b_ = bh >> 4, h_ = bh & 15;
    const int row0 = q0 + wm + g, row1 = row0 + 8;
    __half* d0 = gao + (size_t)(b_ * SEQ + row0) * OCOLS + h_ * DVH;
    __half* d1 = gao + (size_t)(b_ * SEQ + row1) * OCOLS + h_ * DVH;
    #pragma unroll
    for (int nt = 0; nt < 8; nt++) {
        int c = nt * 8 + 2 * tig;
        *(unsigned*)&d0[c] = packh2(Co[nt][0] * sc0, Co[nt][1] * sc0);
        *(unsigned*)&d1[c] = packh2(Co[nt][2] * sc1, Co[nt][3] * sc1);
    }
}

// ---------------- host launch ----------------
extern "C" void kernel_launch(void* const* d_in, const int* in_sizes, int n_in,
                              void* d_out, int out_size)
{
    const float *tokens = nullptr, *Wq = nullptr, *Wkv = nullptr, *Wout = nullptr;
    for (int i = 0; i < n_in; i++) {
        switch (in_sizes[i]) {
            case NTOK * DIM:   tokens = (const float*)d_in[i]; break;
            case DIM * QCOLS:  Wq     = (const float*)d_in[i]; break;
            case DIM * KVCOLS: Wkv    = (const float*)d_in[i]; break;
            case OCOLS * DIM:  Wout   = (const float*)d_in[i]; break;
        }
    }

    __half *tokh, *wc, *wot, *qn, *kn, *vh, *aoh;
    cudaGetSymbolAddress((void**)&tokh, g_tokh);
    cudaGetSymbolAddress((void**)&wc,   g_wc);
    cudaGetSymbolAddress((void**)&wot,  g_wot);
    cudaGetSymbolAddress((void**)&qn,   g_qn);
    cudaGetSymbolAddress((void**)&kn,   g_kn);
    cudaGetSymbolAddress((void**)&vh,   g_vh);
    cudaGetSymbolAddress((void**)&aoh,  g_aoh);

    // dynamic smem opt-in (attribute set, not an allocation; idempotent)
    cudaFuncSetAttribute(proj_gemm, cudaFuncAttributeMaxDynamicSharedMemorySize, SMEM_GEMM);
    cudaFuncSetAttribute(gemm_f16,  cudaFuncAttributeMaxDynamicSharedMemorySize, SMEM_GEMM);

    cvt_f2h<<<(NTOK*DIM/8 + 255)/256, 256>>>(tokens, tokh, NTOK*DIM/8);
    wprep<<<dim3(PCOLS/32, DIM/32), 256>>>(Wq, Wkv, wc);
    wtrans<<<dim3(DIM/32, OCOLS/32), 256>>>(Wout, wot, DIM, OCOLS);

    proj_gemm<<<dim3(PCOLS/128, NTOK/128), 256, SMEM_GEMM>>>(tokh, wc, qn, kn, vh);

    attn_f16<<<dim3(SEQ/128, BATCH*NH), 256>>>(qn, kn, vh, aoh);

    gemm_f16<<<dim3(DIM/128, NTOK/128), 256, SMEM_GEMM>>>(aoh, wot, (float*)d_out, NTOK, DIM, OCOLS);
}